// round 5
// baseline (speedup 1.0000x reference)
#include <cuda_runtime.h>

#define NN 100000
#define EE 1600000
#define EH (EE / 2)
#define FEPS 1e-9f
#define NBLK 391   // (NN + 255) / 256

// ---------------- static device scratch ----------------
__device__ float g_h  [NN * 64];
__device__ float g_P1 [NN * 64];
__device__ float g_P2 [NN * 64];
__device__ float g_P3 [NN * 64];
__device__ float g_q  [NN * 64];   // q[v]  = sum_u beta_u * h[u]
__device__ float g_r  [NN * 64];   // r[v]  = sum_u beta_u * P1[u]
__device__ float g_beta[NN];
__device__ float g_sb  [NN];       // sum_u beta_u
__device__ float g_sb2 [NN];       // sum_u beta_u^2
__device__ int   g_deg [NN];
__device__ int   g_prefix[NN];
__device__ int   g_blocksum[NBLK];
__device__ int   g_blockoff[NBLK];
__device__ int   g_start[NN + 1];
__device__ int   g_cursor[NN];
__device__ int2  g_adjab[EE];      // per CSR slot: {src node u, beta[u]}

__device__ __forceinline__ float2 ld2(const float* p) { return *(const float2*)p; }
__device__ __forceinline__ void   st2(float* p, float2 v) { *(float2*)p = v; }

// ---------------- CSR build ----------------
__global__ void zero_deg_kernel() {
    int i = blockIdx.x * blockDim.x + threadIdx.x;
    if (i < NN) g_deg[i] = 0;
}

// Mirrored pairs: input edge e<EH is (s,d); its mirror (d,s) also exists.
__global__ void deg_kernel(const int* __restrict__ s_arr, const int* __restrict__ d_arr) {
    int e = blockIdx.x * blockDim.x + threadIdx.x;
    if (e >= EH) return;
    atomicAdd(&g_deg[s_arr[e]], 1);
    atomicAdd(&g_deg[d_arr[e]], 1);
}

// Phase 1: per-block exclusive scan of deg (warp shuffle), emit block sums.
__global__ __launch_bounds__(256) void scan1_kernel() {
    __shared__ int warp_sums[8];
    int t = threadIdx.x;
    int i = blockIdx.x * 256 + t;
    int d = (i < NN) ? g_deg[i] : 0;
    int v = d;
    #pragma unroll
    for (int off = 1; off < 32; off <<= 1) {
        int n = __shfl_up_sync(0xffffffffu, v, off);
        if ((t & 31) >= off) v += n;
    }
    if ((t & 31) == 31) warp_sums[t >> 5] = v;
    __syncthreads();
    if (t < 8) {
        int s = warp_sums[t];
        #pragma unroll
        for (int off = 1; off < 8; off <<= 1) {
            int n = __shfl_up_sync(0xffu, s, off);
            if (t >= off) s += n;
        }
        warp_sums[t] = s;
    }
    __syncthreads();
    int base = (t >= 32) ? warp_sums[(t >> 5) - 1] : 0;
    int incl = v + base;
    if (i < NN) g_prefix[i] = incl - d;
    if (t == 255) g_blocksum[blockIdx.x] = incl;
}

// Phase 2: single-block scan of 391 block sums.
__global__ __launch_bounds__(512) void scan2_kernel() {
    __shared__ int s[512];
    int t = threadIdx.x;
    int v = (t < NBLK) ? g_blocksum[t] : 0;
    s[t] = v;
    __syncthreads();
    for (int off = 1; off < 512; off <<= 1) {
        int n = (t >= off) ? s[t - off] : 0;
        __syncthreads();
        s[t] += n;
        __syncthreads();
    }
    if (t < NBLK) g_blockoff[t] = s[t] - v;
}

// Phase 3: finalize start/cursor, compute beta (fused).
__global__ void finish_kernel(const float* __restrict__ lptr) {
    int i = blockIdx.x * blockDim.x + threadIdx.x;
    if (i >= NN) return;
    int st = g_prefix[i] + g_blockoff[i >> 8];
    g_start[i] = st;
    g_cursor[i] = st;
    float lm = __ldg(lptr);
    int d = g_deg[i];
    g_beta[i] = (d == 1) ? 0.0f : lm / ((float)d - 1.0f + FEPS);
    if (i == 0) g_start[NN] = EE;
}

// Fill both CSR buckets per input edge; pack beta of the in-neighbor with it.
__global__ void adjfill_kernel(const int* __restrict__ s_arr, const int* __restrict__ d_arr) {
    int e = blockIdx.x * blockDim.x + threadIdx.x;
    if (e >= EH) return;
    int s = s_arr[e], d = d_arr[e];
    float bs = g_beta[s], bd = g_beta[d];
    int p1 = atomicAdd(&g_cursor[d], 1);
    g_adjab[p1] = make_int2(s, __float_as_int(bs));
    int p2 = atomicAdd(&g_cursor[s], 1);
    g_adjab[p2] = make_int2(d, __float_as_int(bd));
}

// ---------------- h = x @ W + b ----------------
__global__ __launch_bounds__(256) void gemm_kernel(
    const float* __restrict__ x, const float* __restrict__ W, const float* __restrict__ b)
{
    __shared__ float sW[64 * 64];
    __shared__ float sx[32 * 68];
    __shared__ float sb[64];
    int t = threadIdx.x;
    #pragma unroll
    for (int i = t; i < 4096; i += 256) sW[i] = W[i];
    if (t < 64) sb[t] = b[t];
    int row0 = blockIdx.x * 32;
    const float4* xv = (const float4*)(x + row0 * 64);
    #pragma unroll
    for (int i = t; i < 512; i += 256) {
        float4 v = xv[i];
        int r = i >> 4, c4 = i & 15;
        float* d = &sx[r * 68 + c4 * 4];
        d[0] = v.x; d[1] = v.y; d[2] = v.z; d[3] = v.w;
    }
    __syncthreads();
    int r = t >> 3, c0 = (t & 7) * 8;
    float acc[8];
    #pragma unroll
    for (int j = 0; j < 8; j++) acc[j] = sb[c0 + j];
    #pragma unroll
    for (int k = 0; k < 64; k++) {
        float xk = sx[r * 68 + k];
        float4 w0 = *(const float4*)&sW[k * 64 + c0];
        float4 w1 = *(const float4*)&sW[k * 64 + c0 + 4];
        acc[0] += xk * w0.x; acc[1] += xk * w0.y; acc[2] += xk * w0.z; acc[3] += xk * w0.w;
        acc[4] += xk * w1.x; acc[5] += xk * w1.y; acc[6] += xk * w1.z; acc[7] += xk * w1.w;
    }
    float* out = &g_h[(row0 + r) * 64 + c0];
    *(float4*)out       = make_float4(acc[0], acc[1], acc[2], acc[3]);
    *(float4*)(out + 4) = make_float4(acc[4], acc[5], acc[6], acc[7]);
}

// ---------------- gather passes: warp per node, shuffle-staged adjacency ----------------

// G1: s0 = sum h[u]; s1 = sum b_u h[u]; sb, sb2; P1 = a*h + b*s0; q = s1
__global__ __launch_bounds__(256) void g1_kernel(const float* __restrict__ lptr) {
    int w = (blockIdx.x * blockDim.x + threadIdx.x) >> 5;
    int lane = threadIdx.x & 31;
    if (w >= NN) return;
    int beg = g_start[w], end = g_start[w + 1];
    const float* hbase = g_h + lane * 2;
    float2 s0 = make_float2(0.f, 0.f), s1 = make_float2(0.f, 0.f);
    float sbl = 0.f, sb2l = 0.f;
    for (int pos = beg; pos < end; pos += 32) {
        int idx = pos + lane;
        int2 ab = (idx < end) ? g_adjab[idx] : make_int2(0, 0);
        int   u_l = ab.x;
        float b_l = __int_as_float(ab.y);
        sbl += b_l; sb2l += b_l * b_l;
        int cnt = min(32, end - pos);
        int k = 0;
        for (; k + 3 < cnt; k += 4) {
            int u0 = __shfl_sync(0xffffffffu, u_l, k);
            int u1 = __shfl_sync(0xffffffffu, u_l, k + 1);
            int u2 = __shfl_sync(0xffffffffu, u_l, k + 2);
            int u3 = __shfl_sync(0xffffffffu, u_l, k + 3);
            float b0 = __shfl_sync(0xffffffffu, b_l, k);
            float b1 = __shfl_sync(0xffffffffu, b_l, k + 1);
            float b2 = __shfl_sync(0xffffffffu, b_l, k + 2);
            float b3 = __shfl_sync(0xffffffffu, b_l, k + 3);
            float2 h0 = ld2(hbase + u0 * 64);
            float2 h1 = ld2(hbase + u1 * 64);
            float2 h2 = ld2(hbase + u2 * 64);
            float2 h3 = ld2(hbase + u3 * 64);
            s0.x += (h0.x + h1.x) + (h2.x + h3.x);
            s0.y += (h0.y + h1.y) + (h2.y + h3.y);
            s1.x += b0 * h0.x + b1 * h1.x + b2 * h2.x + b3 * h3.x;
            s1.y += b0 * h0.y + b1 * h1.y + b2 * h2.y + b3 * h3.y;
        }
        for (; k < cnt; k++) {
            int u0 = __shfl_sync(0xffffffffu, u_l, k);
            float b0 = __shfl_sync(0xffffffffu, b_l, k);
            float2 h0 = ld2(hbase + u0 * 64);
            s0.x += h0.x; s0.y += h0.y;
            s1.x += b0 * h0.x; s1.y += b0 * h0.y;
        }
    }
    #pragma unroll
    for (int o = 16; o > 0; o >>= 1) {
        sbl  += __shfl_xor_sync(0xffffffffu, sbl,  o);
        sb2l += __shfl_xor_sync(0xffffffffu, sb2l, o);
    }
    float lm = __ldg(lptr);
    float b = g_beta[w];
    float a = (b == 0.f) ? 1.f : (1.f - lm);
    float2 hv = ld2(g_h + w * 64 + lane * 2);
    float2 P1 = make_float2(a * hv.x + b * s0.x, a * hv.y + b * s0.y);
    st2(g_P1 + w * 64 + lane * 2, P1);
    st2(g_q  + w * 64 + lane * 2, s1);
    if (lane == 0) { g_sb[w] = sbl; g_sb2[w] = sb2l; }
}

// G2: s0 = sum P1[u]; s1 = sum b_u P1[u]; m1 = s0 - sb*h; P2 = a*h + b*m1; r = s1
__global__ __launch_bounds__(256) void g2_kernel(const float* __restrict__ lptr) {
    int w = (blockIdx.x * blockDim.x + threadIdx.x) >> 5;
    int lane = threadIdx.x & 31;
    if (w >= NN) return;
    int beg = g_start[w], end = g_start[w + 1];
    const float* pbase = g_P1 + lane * 2;
    float2 s0 = make_float2(0.f, 0.f), s1 = make_float2(0.f, 0.f);
    for (int pos = beg; pos < end; pos += 32) {
        int idx = pos + lane;
        int2 ab = (idx < end) ? g_adjab[idx] : make_int2(0, 0);
        int   u_l = ab.x;
        float b_l = __int_as_float(ab.y);
        int cnt = min(32, end - pos);
        int k = 0;
        for (; k + 3 < cnt; k += 4) {
            int u0 = __shfl_sync(0xffffffffu, u_l, k);
            int u1 = __shfl_sync(0xffffffffu, u_l, k + 1);
            int u2 = __shfl_sync(0xffffffffu, u_l, k + 2);
            int u3 = __shfl_sync(0xffffffffu, u_l, k + 3);
            float b0 = __shfl_sync(0xffffffffu, b_l, k);
            float b1 = __shfl_sync(0xffffffffu, b_l, k + 1);
            float b2 = __shfl_sync(0xffffffffu, b_l, k + 2);
            float b3 = __shfl_sync(0xffffffffu, b_l, k + 3);
            float2 p0 = ld2(pbase + u0 * 64);
            float2 p1 = ld2(pbase + u1 * 64);
            float2 p2 = ld2(pbase + u2 * 64);
            float2 p3 = ld2(pbase + u3 * 64);
            s0.x += (p0.x + p1.x) + (p2.x + p3.x);
            s0.y += (p0.y + p1.y) + (p2.y + p3.y);
            s1.x += b0 * p0.x + b1 * p1.x + b2 * p2.x + b3 * p3.x;
            s1.y += b0 * p0.y + b1 * p1.y + b2 * p2.y + b3 * p3.y;
        }
        for (; k < cnt; k++) {
            int u0 = __shfl_sync(0xffffffffu, u_l, k);
            float b0 = __shfl_sync(0xffffffffu, b_l, k);
            float2 p0 = ld2(pbase + u0 * 64);
            s0.x += p0.x; s0.y += p0.y;
            s1.x += b0 * p0.x; s1.y += b0 * p0.y;
        }
    }
    float lm = __ldg(lptr);
    float b = g_beta[w];
    float a = (b == 0.f) ? 1.f : (1.f - lm);
    float sbv = g_sb[w];
    float2 hv = ld2(g_h + w * 64 + lane * 2);
    float2 m1 = make_float2(s0.x - sbv * hv.x, s0.y - sbv * hv.y);
    float2 P2 = make_float2(a * hv.x + b * m1.x, a * hv.y + b * m1.y);
    st2(g_P2 + w * 64 + lane * 2, P2);
    st2(g_r  + w * 64 + lane * 2, s1);
}

// G3: s0 = sum P2[u]; m2 = s0 + b*q - sb*P1; P3 = a*h + b*m2
__global__ __launch_bounds__(256) void g3_kernel(const float* __restrict__ lptr) {
    int w = (blockIdx.x * blockDim.x + threadIdx.x) >> 5;
    int lane = threadIdx.x & 31;
    if (w >= NN) return;
    int beg = g_start[w], end = g_start[w + 1];
    const float* pbase = g_P2 + lane * 2;
    float2 s0 = make_float2(0.f, 0.f);
    for (int pos = beg; pos < end; pos += 32) {
        int idx = pos + lane;
        int u_l = (idx < end) ? g_adjab[idx].x : 0;
        int cnt = min(32, end - pos);
        int k = 0;
        for (; k + 3 < cnt; k += 4) {
            int u0 = __shfl_sync(0xffffffffu, u_l, k);
            int u1 = __shfl_sync(0xffffffffu, u_l, k + 1);
            int u2 = __shfl_sync(0xffffffffu, u_l, k + 2);
            int u3 = __shfl_sync(0xffffffffu, u_l, k + 3);
            float2 p0 = ld2(pbase + u0 * 64);
            float2 p1 = ld2(pbase + u1 * 64);
            float2 p2 = ld2(pbase + u2 * 64);
            float2 p3 = ld2(pbase + u3 * 64);
            s0.x += (p0.x + p1.x) + (p2.x + p3.x);
            s0.y += (p0.y + p1.y) + (p2.y + p3.y);
        }
        for (; k < cnt; k++) {
            int u0 = __shfl_sync(0xffffffffu, u_l, k);
            float2 p0 = ld2(pbase + u0 * 64);
            s0.x += p0.x; s0.y += p0.y;
        }
    }
    float lm = __ldg(lptr);
    float b = g_beta[w];
    float a = (b == 0.f) ? 1.f : (1.f - lm);
    float sbv = g_sb[w];
    float2 hv  = ld2(g_h  + w * 64 + lane * 2);
    float2 qv  = ld2(g_q  + w * 64 + lane * 2);
    float2 P1v = ld2(g_P1 + w * 64 + lane * 2);
    float2 m2 = make_float2(s0.x + b * qv.x - sbv * P1v.x,
                            s0.y + b * qv.y - sbv * P1v.y);
    float2 P3 = make_float2(a * hv.x + b * m2.x, a * hv.y + b * m2.y);
    st2(g_P3 + w * 64 + lane * 2, P3);
}

// G4: s0 = sum P3[u]; m3 = s0 + b*r - sb*P2 - b*sb2*h; out = x + relu(final)
__global__ __launch_bounds__(256) void g4_kernel(
    const float* __restrict__ x, const float* __restrict__ lptr, float* __restrict__ out)
{
    int w = (blockIdx.x * blockDim.x + threadIdx.x) >> 5;
    int lane = threadIdx.x & 31;
    if (w >= NN) return;
    int beg = g_start[w], end = g_start[w + 1];
    const float* pbase = g_P3 + lane * 2;
    float2 s0 = make_float2(0.f, 0.f);
    for (int pos = beg; pos < end; pos += 32) {
        int idx = pos + lane;
        int u_l = (idx < end) ? g_adjab[idx].x : 0;
        int cnt = min(32, end - pos);
        int k = 0;
        for (; k + 3 < cnt; k += 4) {
            int u0 = __shfl_sync(0xffffffffu, u_l, k);
            int u1 = __shfl_sync(0xffffffffu, u_l, k + 1);
            int u2 = __shfl_sync(0xffffffffu, u_l, k + 2);
            int u3 = __shfl_sync(0xffffffffu, u_l, k + 3);
            float2 p0 = ld2(pbase + u0 * 64);
            float2 p1 = ld2(pbase + u1 * 64);
            float2 p2 = ld2(pbase + u2 * 64);
            float2 p3 = ld2(pbase + u3 * 64);
            s0.x += (p0.x + p1.x) + (p2.x + p3.x);
            s0.y += (p0.y + p1.y) + (p2.y + p3.y);
        }
        for (; k < cnt; k++) {
            int u0 = __shfl_sync(0xffffffffu, u_l, k);
            float2 p0 = ld2(pbase + u0 * 64);
            s0.x += p0.x; s0.y += p0.y;
        }
    }
    float lm = __ldg(lptr);
    float b = g_beta[w];
    float sbv = g_sb[w], sb2v = g_sb2[w];
    float2 hv  = ld2(g_h  + w * 64 + lane * 2);
    float2 rv  = ld2(g_r  + w * 64 + lane * 2);
    float2 P2v = ld2(g_P2 + w * 64 + lane * 2);
    float2 m3 = make_float2(
        s0.x + b * rv.x - sbv * P2v.x - b * sb2v * hv.x,
        s0.y + b * rv.y - sbv * P2v.y - b * sb2v * hv.y);
    int d = g_deg[w];
    float2 y;
    if (d == 0) {
        y = hv;
    } else {
        float s = lm / ((float)d + FEPS);
        y.x = (1.f - lm) * hv.x + s * m3.x;
        y.y = (1.f - lm) * hv.y + s * m3.y;
    }
    y.x = fmaxf(y.x, 0.f); y.y = fmaxf(y.y, 0.f);
    float2 xv = ld2(x + w * 64 + lane * 2);
    st2(out + w * 64 + lane * 2, make_float2(xv.x + y.x, xv.y + y.y));
}

// ---------------- launch ----------------
extern "C" void kernel_launch(void* const* d_in, const int* in_sizes, int n_in,
                              void* d_out, int out_size)
{
    const float* x  = (const float*)d_in[0];
    const int*   ei = (const int*)  d_in[1];
    const float* W  = (const float*)d_in[2];
    const float* b  = (const float*)d_in[3];
    const float* lm = (const float*)d_in[4];
    const int* src = ei;            // concat(s, d)
    const int* dst = ei + EE;       // concat(d, s)

    const int nodeBlocks  = (NN + 255) / 256;   // 391
    const int halfBlocks  = (EH + 255) / 256;
    const int warpBlocks  = (NN * 32) / 256;    // 1 warp per node

    zero_deg_kernel<<<nodeBlocks, 256>>>();
    deg_kernel<<<halfBlocks, 256>>>(src, dst);
    scan1_kernel<<<NBLK, 256>>>();
    scan2_kernel<<<1, 512>>>();
    finish_kernel<<<nodeBlocks, 256>>>(lm);
    adjfill_kernel<<<halfBlocks, 256>>>(src, dst);
    gemm_kernel<<<NN / 32, 256>>>(x, W, b);
    g1_kernel<<<warpBlocks, 256>>>(lm);
    g2_kernel<<<warpBlocks, 256>>>(lm);
    g3_kernel<<<warpBlocks, 256>>>(lm);
    g4_kernel<<<warpBlocks, 256>>>(x, lm, (float*)d_out);
}

// round 7
// speedup vs baseline: 1.0314x; 1.0314x over previous
#include <cuda_runtime.h>
#include <cuda_fp16.h>

#define NN 100000
#define EE 1600000
#define EH (EE / 2)
#define FEPS 1e-9f
#define NBLK 391   // (NN + 255) / 256

// ---------------- static device scratch ----------------
__device__ float  g_h   [NN * 64];   // fp32 h (epilogue / final)
__device__ __half g_h16 [NN * 64];   // fp16 h (gathered)
__device__ __half g_P1h [NN * 64];
__device__ __half g_P2h [NN * 64];
__device__ __half g_P3h [NN * 64];
__device__ float  g_q   [NN * 64];   // q[v] = sum_u beta_u * h[u]
__device__ float  g_r   [NN * 64];   // r[v] = sum_u beta_u * P1[u]
__device__ float  g_beta[NN];
__device__ float  g_sb  [NN];
__device__ float  g_sb2 [NN];
__device__ int    g_deg [NN];
__device__ int    g_prefix[NN];
__device__ int    g_blocksum[NBLK];
__device__ int    g_blockoff[NBLK];
__device__ int    g_start[NN + 1];
__device__ int    g_cursor[NN];
__device__ int    g_adj[EE];

__device__ __forceinline__ float2 ld2(const float* p) { return *(const float2*)p; }
__device__ __forceinline__ void   st2(float* p, float2 v) { *(float2*)p = v; }
__device__ __forceinline__ float2 ldh2(const __half* p) {
    return __half22float2(*(const __half2*)p);
}
__device__ __forceinline__ void sth2(__half* p, float2 v) {
    *(__half2*)p = __floats2half2_rn(v.x, v.y);
}

// ---------------- CSR build ----------------
__global__ void zero_deg_kernel() {
    int i = blockIdx.x * blockDim.x + threadIdx.x;
    if (i < NN) g_deg[i] = 0;
}

// Mirrored pairs: input edge e<EH is (s,d); its mirror (d,s) also exists.
__global__ void deg_kernel(const int* __restrict__ s_arr, const int* __restrict__ d_arr) {
    int e = blockIdx.x * blockDim.x + threadIdx.x;
    if (e >= EH) return;
    atomicAdd(&g_deg[s_arr[e]], 1);
    atomicAdd(&g_deg[d_arr[e]], 1);
}

__global__ __launch_bounds__(256) void scan1_kernel() {
    __shared__ int warp_sums[8];
    int t = threadIdx.x;
    int i = blockIdx.x * 256 + t;
    int d = (i < NN) ? g_deg[i] : 0;
    int v = d;
    #pragma unroll
    for (int off = 1; off < 32; off <<= 1) {
        int n = __shfl_up_sync(0xffffffffu, v, off);
        if ((t & 31) >= off) v += n;
    }
    if ((t & 31) == 31) warp_sums[t >> 5] = v;
    __syncthreads();
    if (t < 8) {
        int s = warp_sums[t];
        #pragma unroll
        for (int off = 1; off < 8; off <<= 1) {
            int n = __shfl_up_sync(0xffu, s, off);
            if (t >= off) s += n;
        }
        warp_sums[t] = s;
    }
    __syncthreads();
    int base = (t >= 32) ? warp_sums[(t >> 5) - 1] : 0;
    int incl = v + base;
    if (i < NN) g_prefix[i] = incl - d;
    if (t == 255) g_blocksum[blockIdx.x] = incl;
}

__global__ __launch_bounds__(512) void scan2_kernel() {
    __shared__ int s[512];
    int t = threadIdx.x;
    int v = (t < NBLK) ? g_blocksum[t] : 0;
    s[t] = v;
    __syncthreads();
    for (int off = 1; off < 512; off <<= 1) {
        int n = (t >= off) ? s[t - off] : 0;
        __syncthreads();
        s[t] += n;
        __syncthreads();
    }
    if (t < NBLK) g_blockoff[t] = s[t] - v;
}

__global__ void finish_kernel(const float* __restrict__ lptr) {
    int i = blockIdx.x * blockDim.x + threadIdx.x;
    if (i >= NN) return;
    int st = g_prefix[i] + g_blockoff[i >> 8];
    g_start[i] = st;
    g_cursor[i] = st;
    float lm = __ldg(lptr);
    int d = g_deg[i];
    g_beta[i] = (d == 1) ? 0.0f : lm / ((float)d - 1.0f + FEPS);
    if (i == 0) g_start[NN] = EE;
}

__global__ void adjfill_kernel(const int* __restrict__ s_arr, const int* __restrict__ d_arr) {
    int e = blockIdx.x * blockDim.x + threadIdx.x;
    if (e >= EH) return;
    int s = s_arr[e], d = d_arr[e];
    int p1 = atomicAdd(&g_cursor[d], 1);
    g_adj[p1] = s;
    int p2 = atomicAdd(&g_cursor[s], 1);
    g_adj[p2] = d;
}

// ---------------- h = x @ W + b  (writes fp32 + fp16 copies) ----------------
__global__ __launch_bounds__(256) void gemm_kernel(
    const float* __restrict__ x, const float* __restrict__ W, const float* __restrict__ b)
{
    __shared__ float sW[64 * 64];
    __shared__ float sx[32 * 68];
    __shared__ float sb[64];
    int t = threadIdx.x;
    #pragma unroll
    for (int i = t; i < 4096; i += 256) sW[i] = W[i];
    if (t < 64) sb[t] = b[t];
    int row0 = blockIdx.x * 32;
    const float4* xv = (const float4*)(x + row0 * 64);
    #pragma unroll
    for (int i = t; i < 512; i += 256) {
        float4 v = xv[i];
        int r = i >> 4, c4 = i & 15;
        float* d = &sx[r * 68 + c4 * 4];
        d[0] = v.x; d[1] = v.y; d[2] = v.z; d[3] = v.w;
    }
    __syncthreads();
    int r = t >> 3, c0 = (t & 7) * 8;
    float acc[8];
    #pragma unroll
    for (int j = 0; j < 8; j++) acc[j] = sb[c0 + j];
    #pragma unroll
    for (int k = 0; k < 64; k++) {
        float xk = sx[r * 68 + k];
        float4 w0 = *(const float4*)&sW[k * 64 + c0];
        float4 w1 = *(const float4*)&sW[k * 64 + c0 + 4];
        acc[0] += xk * w0.x; acc[1] += xk * w0.y; acc[2] += xk * w0.z; acc[3] += xk * w0.w;
        acc[4] += xk * w1.x; acc[5] += xk * w1.y; acc[6] += xk * w1.z; acc[7] += xk * w1.w;
    }
    int o = (row0 + r) * 64 + c0;
    *(float4*)(g_h + o)     = make_float4(acc[0], acc[1], acc[2], acc[3]);
    *(float4*)(g_h + o + 4) = make_float4(acc[4], acc[5], acc[6], acc[7]);
    __half2* h16 = (__half2*)(g_h16 + o);
    h16[0] = __floats2half2_rn(acc[0], acc[1]);
    h16[1] = __floats2half2_rn(acc[2], acc[3]);
    h16[2] = __floats2half2_rn(acc[4], acc[5]);
    h16[3] = __floats2half2_rn(acc[6], acc[7]);
}

// ---------------- gather passes: warp per node, fp16 rows, fp32 accum ----------------

// G1: s0 = sum h[u]; s1 = sum b_u h[u]; sb, sb2; P1 = a*h + b*s0; q = s1
__global__ __launch_bounds__(256) void g1_kernel(const float* __restrict__ lptr) {
    int w = (blockIdx.x * blockDim.x + threadIdx.x) >> 5;
    int lane = threadIdx.x & 31;
    if (w >= NN) return;
    int beg = g_start[w], end = g_start[w + 1];
    const __half* hbase = g_h16 + lane * 2;
    float2 s0 = make_float2(0.f, 0.f), s1 = make_float2(0.f, 0.f);
    float sb = 0.f, sb2 = 0.f;
    int j = beg;
    for (; j + 3 < end; j += 4) {
        int u0 = g_adj[j], u1 = g_adj[j + 1], u2 = g_adj[j + 2], u3 = g_adj[j + 3];
        float b0 = g_beta[u0], b1 = g_beta[u1], b2 = g_beta[u2], b3 = g_beta[u3];
        float2 h0 = ldh2(hbase + u0 * 64);
        float2 h1 = ldh2(hbase + u1 * 64);
        float2 h2 = ldh2(hbase + u2 * 64);
        float2 h3 = ldh2(hbase + u3 * 64);
        s0.x += (h0.x + h1.x) + (h2.x + h3.x);
        s0.y += (h0.y + h1.y) + (h2.y + h3.y);
        s1.x += b0 * h0.x + b1 * h1.x + b2 * h2.x + b3 * h3.x;
        s1.y += b0 * h0.y + b1 * h1.y + b2 * h2.y + b3 * h3.y;
        sb  += (b0 + b1) + (b2 + b3);
        sb2 += (b0 * b0 + b1 * b1) + (b2 * b2 + b3 * b3);
    }
    for (; j < end; j++) {
        int u0 = g_adj[j];
        float b0 = g_beta[u0];
        float2 h0 = ldh2(hbase + u0 * 64);
        s0.x += h0.x; s0.y += h0.y;
        s1.x += b0 * h0.x; s1.y += b0 * h0.y;
        sb += b0; sb2 += b0 * b0;
    }
    float lm = __ldg(lptr);
    float b = g_beta[w];
    float a = (b == 0.f) ? 1.f : (1.f - lm);
    float2 hv = ld2(g_h + w * 64 + lane * 2);
    float2 P1 = make_float2(a * hv.x + b * s0.x, a * hv.y + b * s0.y);
    sth2(g_P1h + w * 64 + lane * 2, P1);
    st2(g_q + w * 64 + lane * 2, s1);
    if (lane == 0) { g_sb[w] = sb; g_sb2[w] = sb2; }
}

// G2: s0 = sum P1[u]; s1 = sum b_u P1[u]; m1 = s0 - sb*h; P2 = a*h + b*m1; r = s1
__global__ __launch_bounds__(256) void g2_kernel(const float* __restrict__ lptr) {
    int w = (blockIdx.x * blockDim.x + threadIdx.x) >> 5;
    int lane = threadIdx.x & 31;
    if (w >= NN) return;
    int beg = g_start[w], end = g_start[w + 1];
    const __half* pbase = g_P1h + lane * 2;
    float2 s0 = make_float2(0.f, 0.f), s1 = make_float2(0.f, 0.f);
    int j = beg;
    for (; j + 3 < end; j += 4) {
        int u0 = g_adj[j], u1 = g_adj[j + 1], u2 = g_adj[j + 2], u3 = g_adj[j + 3];
        float b0 = g_beta[u0], b1 = g_beta[u1], b2 = g_beta[u2], b3 = g_beta[u3];
        float2 p0 = ldh2(pbase + u0 * 64);
        float2 p1 = ldh2(pbase + u1 * 64);
        float2 p2 = ldh2(pbase + u2 * 64);
        float2 p3 = ldh2(pbase + u3 * 64);
        s0.x += (p0.x + p1.x) + (p2.x + p3.x);
        s0.y += (p0.y + p1.y) + (p2.y + p3.y);
        s1.x += b0 * p0.x + b1 * p1.x + b2 * p2.x + b3 * p3.x;
        s1.y += b0 * p0.y + b1 * p1.y + b2 * p2.y + b3 * p3.y;
    }
    for (; j < end; j++) {
        int u0 = g_adj[j];
        float b0 = g_beta[u0];
        float2 p0 = ldh2(pbase + u0 * 64);
        s0.x += p0.x; s0.y += p0.y;
        s1.x += b0 * p0.x; s1.y += b0 * p0.y;
    }
    float lm = __ldg(lptr);
    float b = g_beta[w];
    float a = (b == 0.f) ? 1.f : (1.f - lm);
    float sbv = g_sb[w];
    float2 hv = ld2(g_h + w * 64 + lane * 2);
    float2 m1 = make_float2(s0.x - sbv * hv.x, s0.y - sbv * hv.y);
    float2 P2 = make_float2(a * hv.x + b * m1.x, a * hv.y + b * m1.y);
    sth2(g_P2h + w * 64 + lane * 2, P2);
    st2(g_r + w * 64 + lane * 2, s1);
}

// G3: s0 = sum P2[u]; m2 = s0 + b*q - sb*P1; P3 = a*h + b*m2
__global__ __launch_bounds__(256) void g3_kernel(const float* __restrict__ lptr) {
    int w = (blockIdx.x * blockDim.x + threadIdx.x) >> 5;
    int lane = threadIdx.x & 31;
    if (w >= NN) return;
    int beg = g_start[w], end = g_start[w + 1];
    const __half* pbase = g_P2h + lane * 2;
    float2 s0 = make_float2(0.f, 0.f);
    int j = beg;
    for (; j + 3 < end; j += 4) {
        int u0 = g_adj[j], u1 = g_adj[j + 1], u2 = g_adj[j + 2], u3 = g_adj[j + 3];
        float2 p0 = ldh2(pbase + u0 * 64);
        float2 p1 = ldh2(pbase + u1 * 64);
        float2 p2 = ldh2(pbase + u2 * 64);
        float2 p3 = ldh2(pbase + u3 * 64);
        s0.x += (p0.x + p1.x) + (p2.x + p3.x);
        s0.y += (p0.y + p1.y) + (p2.y + p3.y);
    }
    for (; j < end; j++) {
        int u0 = g_adj[j];
        float2 p0 = ldh2(pbase + u0 * 64);
        s0.x += p0.x; s0.y += p0.y;
    }
    float lm = __ldg(lptr);
    float b = g_beta[w];
    float a = (b == 0.f) ? 1.f : (1.f - lm);
    float sbv = g_sb[w];
    float2 hv  = ld2 (g_h   + w * 64 + lane * 2);
    float2 qv  = ld2 (g_q   + w * 64 + lane * 2);
    float2 P1v = ldh2(g_P1h + w * 64 + lane * 2);
    float2 m2 = make_float2(s0.x + b * qv.x - sbv * P1v.x,
                            s0.y + b * qv.y - sbv * P1v.y);
    float2 P3 = make_float2(a * hv.x + b * m2.x, a * hv.y + b * m2.y);
    sth2(g_P3h + w * 64 + lane * 2, P3);
}

// G4: s0 = sum P3[u]; m3 = s0 + b*r - sb*P2 - b*sb2*h; out = x + relu(final)
__global__ __launch_bounds__(256) void g4_kernel(
    const float* __restrict__ x, const float* __restrict__ lptr, float* __restrict__ out)
{
    int w = (blockIdx.x * blockDim.x + threadIdx.x) >> 5;
    int lane = threadIdx.x & 31;
    if (w >= NN) return;
    int beg = g_start[w], end = g_start[w + 1];
    const __half* pbase = g_P3h + lane * 2;
    float2 s0 = make_float2(0.f, 0.f);
    int j = beg;
    for (; j + 3 < end; j += 4) {
        int u0 = g_adj[j], u1 = g_adj[j + 1], u2 = g_adj[j + 2], u3 = g_adj[j + 3];
        float2 p0 = ldh2(pbase + u0 * 64);
        float2 p1 = ldh2(pbase + u1 * 64);
        float2 p2 = ldh2(pbase + u2 * 64);
        float2 p3 = ldh2(pbase + u3 * 64);
        s0.x += (p0.x + p1.x) + (p2.x + p3.x);
        s0.y += (p0.y + p1.y) + (p2.y + p3.y);
    }
    for (; j < end; j++) {
        int u0 = g_adj[j];
        float2 p0 = ldh2(pbase + u0 * 64);
        s0.x += p0.x; s0.y += p0.y;
    }
    float lm = __ldg(lptr);
    float b = g_beta[w];
    float sbv = g_sb[w], sb2v = g_sb2[w];
    float2 hv  = ld2 (g_h   + w * 64 + lane * 2);
    float2 rv  = ld2 (g_r   + w * 64 + lane * 2);
    float2 P2v = ldh2(g_P2h + w * 64 + lane * 2);
    float2 m3 = make_float2(
        s0.x + b * rv.x - sbv * P2v.x - b * sb2v * hv.x,
        s0.y + b * rv.y - sbv * P2v.y - b * sb2v * hv.y);
    int d = g_deg[w];
    float2 y;
    if (d == 0) {
        y = hv;
    } else {
        float s = lm / ((float)d + FEPS);
        y.x = (1.f - lm) * hv.x + s * m3.x;
        y.y = (1.f - lm) * hv.y + s * m3.y;
    }
    y.x = fmaxf(y.x, 0.f); y.y = fmaxf(y.y, 0.f);
    float2 xv = ld2(x + w * 64 + lane * 2);
    st2(out + w * 64 + lane * 2, make_float2(xv.x + y.x, xv.y + y.y));
}

// ---------------- launch ----------------
extern "C" void kernel_launch(void* const* d_in, const int* in_sizes, int n_in,
                              void* d_out, int out_size)
{
    const float* x  = (const float*)d_in[0];
    const int*   ei = (const int*)  d_in[1];
    const float* W  = (const float*)d_in[2];
    const float* b  = (const float*)d_in[3];
    const float* lm = (const float*)d_in[4];
    const int* src = ei;            // concat(s, d)
    const int* dst = ei + EE;       // concat(d, s)

    const int nodeBlocks = (NN + 255) / 256;   // 391
    const int halfBlocks = (EH + 255) / 256;
    const int warpBlocks = (NN * 32) / 256;    // 1 warp per node

    zero_deg_kernel<<<nodeBlocks, 256>>>();
    deg_kernel<<<halfBlocks, 256>>>(src, dst);
    scan1_kernel<<<NBLK, 256>>>();
    scan2_kernel<<<1, 512>>>();
    finish_kernel<<<nodeBlocks, 256>>>(lm);
    adjfill_kernel<<<halfBlocks, 256>>>(src, dst);
    gemm_kernel<<<NN / 32, 256>>>(x, W, b);
    g1_kernel<<<warpBlocks, 256>>>(lm);
    g2_kernel<<<warpBlocks, 256>>>(lm);
    g3_kernel<<<warpBlocks, 256>>>(lm);
    g4_kernel<<<warpBlocks, 256>>>(x, lm, (float*)d_out);
}